// round 10
// baseline (speedup 1.0000x reference)
#include <cuda_runtime.h>
#include <math.h>
#include <stdint.h>

#define N_NODES 12800
#define N_EDGES 204800
#define DIM 16
#define CHUNK 256

typedef unsigned long long ull;

// ---------------- scratch (static device memory, no allocs) ----------------
__device__ float g_out[N_NODES * DIM];
__device__ float g_hs[N_EDGES * DIM];       // edge hidden, rank-sorted order
__device__ int   g_dst[N_EDGES];            // dst node id per rank-sorted slot
__device__ float g_aggr0[N_NODES * DIM];    // aggregation ping-pong (RED targets)
__device__ float g_aggr1[N_NODES * DIM];    // zero at load; each reader re-zeroes
__device__ int   g_src_cnt[N_NODES];        // zero at load; re-zeroed by k_scan
__device__ int   g_dst_cnt[N_NODES];        // zero at load; re-zeroed by k_scan
__device__ int   g_nid[N_NODES];            // rank -> node id (degree-sorted)
__device__ int   g_roff[N_NODES + 1];       // rank -> edge offset
__device__ int   g_src_cur[N_NODES];        // node -> scatter cursor
__device__ float g_invdeg[N_NODES];

// ---------------- setup ----------------
// blocks [0,800): edge histograms; blocks [800,1600): lin0.
__global__ void k_hist(const float* __restrict__ x, const int* __restrict__ ei,
                       const float* __restrict__ l0w, const float* __restrict__ l0b) {
    int gb = blockIdx.x;
    if (gb < N_EDGES / 256) {
        int e = gb * 256 + threadIdx.x;
        atomicAdd(&g_src_cnt[ei[e]], 1);
        atomicAdd(&g_dst_cnt[ei[N_EDGES + e]], 1);
    } else {
        int i = (gb - N_EDGES / 256) * 256 + threadIdx.x;
        int n = i >> 4, k = i & 15;
        float acc = l0b[k];
#pragma unroll
        for (int c = 0; c < 3; ++c) acc += x[n * 3 + c] * l0w[k * 3 + c];
        g_out[i] = fmaxf(acc, 0.0f);
    }
}

// block 0: counting-sort nodes by out-degree -> rank, rank edge offsets,
//          per-node scatter cursors. Re-zeroes src counts.
// block 1: invdeg from dst counts; re-zeroes dst counts.
__global__ void k_scan() {
    int tid = threadIdx.x;
    if (blockIdx.x == 1) {
        for (int i = tid; i < N_NODES; i += 1024) {
            g_invdeg[i] = 1.0f / fmaxf((float)g_dst_cnt[i], 1.0f);
            g_dst_cnt[i] = 0;
        }
        return;
    }
    __shared__ int hist[1024];
    __shared__ int nbase[1024];   // rank base per degree bin
    __shared__ int ebase[1024];   // edge offset base per degree bin
    __shared__ int wc[32], we[32];
    int lane = tid & 31, wid = tid >> 5;

    hist[tid] = 0;
    __syncthreads();
    for (int n = tid; n < N_NODES; n += 1024) {
        int d = g_src_cnt[n]; if (d > 1023) d = 1023;
        atomicAdd(&hist[d], 1);
    }
    __syncthreads();
    int c = hist[tid];
    int ec = c * tid;
    int ci = c, ei2 = ec;
#pragma unroll
    for (int s = 1; s < 32; s <<= 1) {
        int v = __shfl_up_sync(0xffffffffu, ci, s);
        int w2 = __shfl_up_sync(0xffffffffu, ei2, s);
        if (lane >= s) { ci += v; ei2 += w2; }
    }
    if (lane == 31) { wc[wid] = ci; we[wid] = ei2; }
    __syncthreads();
    if (wid == 0) {
        int v = wc[lane], iv = v, e = we[lane], ie = e;
#pragma unroll
        for (int s = 1; s < 32; s <<= 1) {
            int t1 = __shfl_up_sync(0xffffffffu, iv, s);
            int t2 = __shfl_up_sync(0xffffffffu, ie, s);
            if (lane >= s) { iv += t1; ie += t2; }
        }
        wc[lane] = iv - v; we[lane] = ie - e;
    }
    __syncthreads();
    nbase[tid] = wc[wid] + (ci - c);
    ebase[tid] = we[wid] + (ei2 - ec);
    hist[tid] = 0;                 // reuse as intra-bin cursor
    __syncthreads();
    for (int n = tid; n < N_NODES; n += 1024) {
        int d = g_src_cnt[n]; if (d > 1023) d = 1023;
        g_src_cnt[n] = 0;          // re-zero for next kernel_launch call
        int t = atomicAdd(&hist[d], 1);
        int rank = nbase[d] + t;
        int eoff = ebase[d] + t * d;
        g_nid[rank] = n;
        g_roff[rank] = eoff;
        g_src_cur[n] = eoff;
    }
    if (tid == 0) g_roff[N_NODES] = N_EDGES;
}

// Per edge: place into rank-sorted slot p, record dst, compute edge hidden
// h = relu(ea @ nn1_w^T + nn1_b) directly into g_hs[p].
__global__ void k_scatter(const int* __restrict__ ei, const float* __restrict__ ea,
                          const float* __restrict__ n1w, const float* __restrict__ n1b) {
    int e = blockIdx.x * blockDim.x + threadIdx.x;
    if (e >= N_EDGES) return;
    int s = ei[e], d = ei[N_EDGES + e];
    int p = atomicAdd(&g_src_cur[s], 1);
    g_dst[p] = d;
    float4 a = __ldg((const float4*)&ea[e * 4]);
    float* hd = &g_hs[p * DIM];
#pragma unroll
    for (int j = 0; j < 16; j += 4) {
        float4 h;
        h.x = fmaxf(n1b[j + 0] + a.x * n1w[(j + 0) * 4] + a.y * n1w[(j + 0) * 4 + 1] +
                    a.z * n1w[(j + 0) * 4 + 2] + a.w * n1w[(j + 0) * 4 + 3], 0.0f);
        h.y = fmaxf(n1b[j + 1] + a.x * n1w[(j + 1) * 4] + a.y * n1w[(j + 1) * 4 + 1] +
                    a.z * n1w[(j + 1) * 4 + 2] + a.w * n1w[(j + 1) * 4 + 3], 0.0f);
        h.z = fmaxf(n1b[j + 2] + a.x * n1w[(j + 2) * 4] + a.y * n1w[(j + 2) * 4 + 1] +
                    a.z * n1w[(j + 2) * 4 + 2] + a.w * n1w[(j + 2) * 4 + 3], 0.0f);
        h.w = fmaxf(n1b[j + 3] + a.x * n1w[(j + 3) * 4] + a.y * n1w[(j + 3) * 4 + 1] +
                    a.z * n1w[(j + 3) * 4 + 2] + a.w * n1w[(j + 3) * 4 + 3], 0.0f);
        *(float4*)&hd[j] = h;
    }
}

// ---------------- fused per-round kernel ----------------
// 512 threads = 16 warps = 16 RANKS (consecutive, so near-equal degree).
// Phase 1 (r>0): aggr read (+re-zero) + root + ReLU + GRU.
// Phase 2: each half-warp keeps 4 P j-pairs in f32x2 regs.
// Phase 3: double-buffered 256-edge chunks (buf0 aliases dead w2 smem);
// per edge: halves split h (1-wf LDS.128s), shfl_xor combine, 4x shfl.idx
// gather, lanes 0-3 issue red.global.add.v4.f32.
__global__ void __launch_bounds__(512) k_round(
    const float* __restrict__ w2, const float* __restrict__ b2,
    const float* __restrict__ cr, const float* __restrict__ cb,
    const float* __restrict__ wih, const float* __restrict__ whh,
    const float* __restrict__ bih, const float* __restrict__ bhh,
    float* __restrict__ aggr_r, float* __restrict__ aggr_w, int r) {
    __shared__ __align__(16) char s_raw[16384];    // w2 packed, then h buf 0
    __shared__ __align__(16) char s_raw2[16384];   // h buf 1
    __shared__ int s_db[2][CHUNK];
    __shared__ float s_b2[256];
    __shared__ float s_cr[256];
    __shared__ float s_wih[768];                   // transposed [d][gate]
    __shared__ float s_whh[768];
    __shared__ float s_out[16][16];
    __shared__ float s_m[16][16];
    ull* s_w2p = (ull*)s_raw;                      // [d][jj][k]
    float4* s_h4a = (float4*)s_raw;
    float4* s_h4b = (float4*)s_raw2;

    int tid = threadIdx.x;
    int lane = tid & 31, k = lane & 15, par = lane >> 4, w = tid >> 5;
    int rank = blockIdx.x * 16 + w;
    int n = g_nid[rank];

    for (int i = tid; i < 4096; i += 512) {
        int d = i >> 8, kk = (i >> 4) & 15, j = i & 15;
        ((float*)&s_w2p[(d * 8 + (j >> 1)) * 16 + kk])[j & 1] = w2[i];
    }
    if (tid < 256) { s_b2[tid] = b2[tid]; s_cr[tid] = cr[tid]; }
    for (int i = tid; i < 768; i += 512) {
        int rr = i >> 4, d = i & 15;
        s_wih[d * 48 + rr] = wih[i];
        s_whh[d * 48 + rr] = whh[i];
    }
    float hprev = g_out[n * DIM + k];
    if (par == 0) s_out[w][k] = hprev;
    __syncthreads();

    if (r > 0) {
        float v = aggr_r[n * DIM + k];
        if (par == 0) aggr_r[n * DIM + k] = 0.0f;  // zero for round r+1's REDs
        float acc = v * g_invdeg[n] + cb[k];
#pragma unroll
        for (int d = 0; d < DIM; ++d) acc += s_out[w][d] * s_cr[d * 16 + k];
        float m = fmaxf(acc, 0.0f);
        __syncwarp();
        if (par == 0) s_m[w][k] = m;
        __syncwarp();

        float gr = bih[k], gz = bih[k + 16], gn = bih[k + 32];
        float hr = bhh[k], hz = bhh[k + 16], hn = bhh[k + 32];
#pragma unroll
        for (int d = 0; d < DIM; ++d) {
            float md = s_m[w][d], hd = s_out[w][d];
            gr += md * s_wih[d * 48 + k];
            gz += md * s_wih[d * 48 + k + 16];
            gn += md * s_wih[d * 48 + k + 32];
            hr += hd * s_whh[d * 48 + k];
            hz += hd * s_whh[d * 48 + k + 16];
            hn += hd * s_whh[d * 48 + k + 32];
        }
        float rr = 1.0f / (1.0f + expf(-(gr + hr)));
        float zz = 1.0f / (1.0f + expf(-(gz + hz)));
        float nh = tanhf(gn + rr * hn);
        float hnew = (1.0f - zz) * nh + zz * hprev;
        __syncwarp();
        if (par == 0) {
            s_out[w][k] = hnew;
            g_out[n * DIM + k] = hnew;
        }
        __syncwarp();
    }

    // ---- P-compute: this half's 4 j-pairs of P[k][:] in f32x2 regs ----
    ull p2[4];
    float xb = 0.0f;
#pragma unroll
    for (int jj = 0; jj < 4; ++jj) p2[jj] = 0ull;
#pragma unroll
    for (int d = 0; d < 16; ++d) {
        float od = s_out[w][d];
        ull od2;
        asm("mov.b64 %0,{%1,%1};" : "=l"(od2) : "f"(od));
        xb += od * s_b2[d * 16 + k];
#pragma unroll
        for (int jj = 0; jj < 4; ++jj) {
            ull wv = s_w2p[(d * 8 + par * 4 + jj) * 16 + k];
            asm("fma.rn.f32x2 %0,%1,%2,%0;" : "+l"(p2[jj]) : "l"(od2), "l"(wv));
        }
    }

    // ---- edge mainloop: double-buffered chunks ----
    int bn = g_roff[rank], en = g_roff[rank + 1];
    int E0 = g_roff[blockIdx.x * 16];
    int E1 = g_roff[blockIdx.x * 16 + 16];
    const float4* hs4 = (const float4*)g_hs;

#define STAGE(cb_, buf_) do {                                              \
        int ce_ = (cb_) + CHUNK < E1 ? (cb_) + CHUNK : E1;                 \
        int cnt4_ = (ce_ - (cb_)) * 4;                                     \
        float4* dh_ = (buf_) ? s_h4b : s_h4a;                              \
        for (int i4_ = tid; i4_ < cnt4_; i4_ += 512)                       \
            dh_[i4_] = hs4[(cb_) * 4 + i4_];                               \
        if (tid < ce_ - (cb_)) s_db[buf_][tid] = g_dst[(cb_) + tid];       \
    } while (0)

    __syncthreads();                  // w2 reads done (s_raw becomes h buf 0)
    if (E0 < E1) {
        STAGE(E0, 0);
        __syncthreads();
        int c = 0;
        for (int cbase = E0; cbase < E1; cbase += CHUNK, ++c) {
            int nxt = cbase + CHUNK;
            if (nxt < E1) STAGE(nxt, (c + 1) & 1);
            const ulonglong2* hb = (c & 1) ? (const ulonglong2*)s_raw2
                                           : (const ulonglong2*)s_raw;
            const int* sd = s_db[c & 1];
            int ce = nxt < E1 ? nxt : E1;
            int lo_ = bn > cbase ? bn : cbase;
            int hi_ = en < ce ? en : ce;
            for (int i = lo_; i < hi_; ++i) {
                int li = i - cbase;
                int dst = sd[li];                       // warp-uniform
                ulonglong2 X = hb[li * 4 + par * 2];    // 2 addrs/warp
                ulonglong2 Y = hb[li * 4 + par * 2 + 1];
                ull a;
                asm("mul.rn.f32x2 %0,%1,%2;" : "=l"(a) : "l"(X.x), "l"(p2[0]));
                asm("fma.rn.f32x2 %0,%1,%2,%0;" : "+l"(a) : "l"(X.y), "l"(p2[1]));
                asm("fma.rn.f32x2 %0,%1,%2,%0;" : "+l"(a) : "l"(Y.x), "l"(p2[2]));
                asm("fma.rn.f32x2 %0,%1,%2,%0;" : "+l"(a) : "l"(Y.y), "l"(p2[3]));
                float lo_f, hi_f;
                asm("mov.b64 {%0,%1},%2;" : "=f"(lo_f), "=f"(hi_f) : "l"(a));
                float t = lo_f + hi_f;
                t += __shfl_xor_sync(0xffffffffu, t, 16);   // combine halves
                t += xb;
                int src0 = lane << 2;                   // gather 4 k per lane
                float v0 = __shfl_sync(0xffffffffu, t, src0);
                float v1 = __shfl_sync(0xffffffffu, t, src0 + 1);
                float v2 = __shfl_sync(0xffffffffu, t, src0 + 2);
                float v3 = __shfl_sync(0xffffffffu, t, src0 + 3);
                const float* pdst = &aggr_w[dst * DIM + (lane << 2)];
                asm volatile(
                    "{\n\t.reg .pred p;\n\t"
                    "setp.lt.u32 p, %5, 4;\n\t"
                    "@p red.global.add.v4.f32 [%0], {%1,%2,%3,%4};\n\t}"
                    :: "l"(pdst), "f"(v0), "f"(v1), "f"(v2), "f"(v3), "r"(lane)
                    : "memory");
            }
            __syncthreads();
        }
    }
#undef STAGE
}

// ---------------- final GRU-only kernel -> d_out ----------------
__global__ void k_fin(float* __restrict__ aggr_r,
                      const float* __restrict__ cr, const float* __restrict__ cb,
                      const float* __restrict__ wih, const float* __restrict__ whh,
                      const float* __restrict__ bih, const float* __restrict__ bhh,
                      float* __restrict__ outw) {
    __shared__ float s_cr[DIM * DIM];
    __shared__ float s_wih[DIM * 3 * DIM];
    __shared__ float s_whh[DIM * 3 * DIM];
    __shared__ float s_out[16][DIM];
    __shared__ float s_m[16][DIM];
    int tid = threadIdx.x;
    for (int i = tid; i < DIM * DIM; i += 256) s_cr[i] = cr[i];
    for (int i = tid; i < 3 * DIM * DIM; i += 256) {
        int r = i >> 4, d = i & 15;
        s_wih[d * 48 + r] = wih[i];
        s_whh[d * 48 + r] = whh[i];
    }
    int ln = tid >> 4, k = tid & 15;
    int n = blockIdx.x * 16 + ln;
    float hprev = g_out[n * DIM + k];
    s_out[ln][k] = hprev;
    __syncthreads();

    float v = aggr_r[n * DIM + k];
    aggr_r[n * DIM + k] = 0.0f;                   // restore zeros for next call
    float acc = v * g_invdeg[n] + cb[k];
#pragma unroll
    for (int d = 0; d < DIM; ++d) acc += s_out[ln][d] * s_cr[d * DIM + k];
    float m = fmaxf(acc, 0.0f);
    s_m[ln][k] = m;
    __syncthreads();

    float gr = bih[k], gz = bih[k + 16], gn = bih[k + 32];
    float hr = bhh[k], hz = bhh[k + 16], hn = bhh[k + 32];
#pragma unroll
    for (int d = 0; d < DIM; ++d) {
        float md = s_m[ln][d], hd = s_out[ln][d];
        gr += md * s_wih[d * 48 + k];
        gz += md * s_wih[d * 48 + k + 16];
        gn += md * s_wih[d * 48 + k + 32];
        hr += hd * s_whh[d * 48 + k];
        hz += hd * s_whh[d * 48 + k + 16];
        hn += hd * s_whh[d * 48 + k + 32];
    }
    float r = 1.0f / (1.0f + expf(-(gr + hr)));
    float z = 1.0f / (1.0f + expf(-(gz + hz)));
    float nh = tanhf(gn + r * hn);
    outw[n * DIM + k] = (1.0f - z) * nh + z * hprev;
}

// ---------------- host launcher ----------------
extern "C" void kernel_launch(void* const* d_in, const int* in_sizes, int n_in,
                              void* d_out, int out_size) {
    const float* x         = (const float*)d_in[0];
    const int*   ei        = (const int*)  d_in[1];
    const float* ea        = (const float*)d_in[2];
    const float* lin0_w    = (const float*)d_in[3];
    const float* lin0_b    = (const float*)d_in[4];
    const float* nn1_w     = (const float*)d_in[5];
    const float* nn1_b     = (const float*)d_in[6];
    const float* nn2_w     = (const float*)d_in[7];
    const float* nn2_b     = (const float*)d_in[8];
    const float* conv_root = (const float*)d_in[9];
    const float* conv_bias = (const float*)d_in[10];
    const float* w_ih      = (const float*)d_in[11];
    const float* w_hh      = (const float*)d_in[12];
    const float* b_ih      = (const float*)d_in[13];
    const float* b_hh      = (const float*)d_in[14];

    float *a0 = nullptr, *a1 = nullptr;
    cudaGetSymbolAddress((void**)&a0, g_aggr0);
    cudaGetSymbolAddress((void**)&a1, g_aggr1);

    k_hist<<<N_EDGES / 256 + (N_NODES * DIM) / 256, 256>>>(x, ei, lin0_w, lin0_b);
    k_scan<<<2, 1024>>>();
    k_scatter<<<(N_EDGES + 255) / 256, 256>>>(ei, ea, nn1_w, nn1_b);

    for (int r = 0; r < 6; ++r) {
        float* ar = ((r - 1) & 1) ? a1 : a0;   // buffer round r-1 REDed into
        float* aw = (r & 1) ? a1 : a0;
        k_round<<<N_NODES / 16, 512>>>(nn2_w, nn2_b, conv_root, conv_bias,
                                       w_ih, w_hh, b_ih, b_hh, ar, aw, r);
    }
    k_fin<<<N_NODES / 16, 256>>>(a1, conv_root, conv_bias, w_ih, w_hh,
                                 b_ih, b_hh, (float*)d_out);
}